// round 1
// baseline (speedup 1.0000x reference)
#include <cuda_runtime.h>
#include <math.h>
#include <stdint.h>

// Problem constants
#define BB   2
#define LL   2048
#define DD   1024
#define HH   16
#define HDIM 64

// Scratch for projected Q,K,V  (each 2*2048*1024 fp32 = 16 MB, static device mem)
__device__ float g_q[BB * LL * DD];
__device__ float g_k[BB * LL * DD];
__device__ float g_v[BB * LL * DD];

// ---------------------------------------------------------------------------
// Kernel 1: QKV projection.  Y = X @ W + b  for W in {Wq, Wk, Wv} (blockIdx.z)
// X: [4096, 1024] row-major, W: [1024, 1024] row-major.
// Tile: BM=128, BN=128, BK=8. 256 threads, 8x8 per thread (split-tile mapping).
// ---------------------------------------------------------------------------
__global__ __launch_bounds__(256) void qkv_gemm_kernel(
    const float* __restrict__ X,
    const float* __restrict__ Wq, const float* __restrict__ bq,
    const float* __restrict__ Wk, const float* __restrict__ bk,
    const float* __restrict__ Wv, const float* __restrict__ bv)
{
    // As stored transposed: As[k][m], stride 132 (conflict-free STS, verified)
    __shared__ float As[8 * 132];
    __shared__ float Bs[8 * 132];

    const float* W;
    const float* bias;
    float* out;
    if (blockIdx.z == 0)      { W = Wq; bias = bq; out = g_q; }
    else if (blockIdx.z == 1) { W = Wk; bias = bk; out = g_k; }
    else                      { W = Wv; bias = bv; out = g_v; }

    const int tid = threadIdx.x;
    const int m0 = blockIdx.y * 128;
    const int n0 = blockIdx.x * 128;

    const int tr = tid >> 4;       // 0..15
    const int tc = tid & 15;       // 0..15

    // A-tile loader: each thread one float4 (row amr, cols akc..akc+3)
    const int amr = tid >> 1;
    const int akc = (tid & 1) * 4;
    // B-tile loader: each thread one float4 (row bkr, cols bnc..bnc+3)
    const int bkr = tid >> 5;
    const int bnc = (tid & 31) * 4;

    float acc[8][8];
#pragma unroll
    for (int i = 0; i < 8; i++)
#pragma unroll
        for (int j = 0; j < 8; j++) acc[i][j] = 0.0f;

    for (int k0 = 0; k0 < DD; k0 += 8) {
        float4 av = *(const float4*)(X + (size_t)(m0 + amr) * DD + k0 + akc);
        float4 bv4 = *(const float4*)(W + (size_t)(k0 + bkr) * DD + n0 + bnc);
        As[(akc + 0) * 132 + amr] = av.x;
        As[(akc + 1) * 132 + amr] = av.y;
        As[(akc + 2) * 132 + amr] = av.z;
        As[(akc + 3) * 132 + amr] = av.w;
        *(float4*)&Bs[bkr * 132 + bnc] = bv4;
        __syncthreads();

#pragma unroll
        for (int kk = 0; kk < 8; kk++) {
            float4 a0 = *(const float4*)&As[kk * 132 + tr * 4];
            float4 a1 = *(const float4*)&As[kk * 132 + 64 + tr * 4];
            float4 b0 = *(const float4*)&Bs[kk * 132 + tc * 4];
            float4 b1 = *(const float4*)&Bs[kk * 132 + 64 + tc * 4];
            float a[8] = {a0.x, a0.y, a0.z, a0.w, a1.x, a1.y, a1.z, a1.w};
            float b[8] = {b0.x, b0.y, b0.z, b0.w, b1.x, b1.y, b1.z, b1.w};
#pragma unroll
            for (int i = 0; i < 8; i++)
#pragma unroll
                for (int j = 0; j < 8; j++)
                    acc[i][j] = fmaf(a[i], b[j], acc[i][j]);
        }
        __syncthreads();
    }

    // Epilogue: rows {tr*4+i, 64+tr*4+i}, cols {tc*4+j, 64+tc*4+j}
    float4 bias0 = *(const float4*)(bias + n0 + tc * 4);
    float4 bias1 = *(const float4*)(bias + n0 + 64 + tc * 4);
#pragma unroll
    for (int i = 0; i < 8; i++) {
        int mi = m0 + ((i < 4) ? (tr * 4 + i) : (64 + tr * 4 + (i - 4)));
        float4 r0, r1;
        r0.x = acc[i][0] + bias0.x; r0.y = acc[i][1] + bias0.y;
        r0.z = acc[i][2] + bias0.z; r0.w = acc[i][3] + bias0.w;
        r1.x = acc[i][4] + bias1.x; r1.y = acc[i][5] + bias1.y;
        r1.z = acc[i][6] + bias1.z; r1.w = acc[i][7] + bias1.w;
        *(float4*)(out + (size_t)mi * DD + n0 + tc * 4)      = r0;
        *(float4*)(out + (size_t)mi * DD + n0 + 64 + tc * 4) = r1;
    }
}

// ---------------------------------------------------------------------------
// Kernel 2: flash attention.  grid (L/64, H, B), 256 threads per CTA.
// BQ = BKV = 64, HD = 64. Online softmax in base-2 (log2e folded into scales).
// Each thread owns rows {ty+16i} and cols {tx+16j} (strided for conflict-free
// smem access). Row statistics reduced across the 16-lane tx group via shfl.
// ---------------------------------------------------------------------------
#define TSTRIDE 68   // smem row stride (floats): 16B aligned, <=2-way conflicts
#define ATTN_SMEM (4 * 64 * TSTRIDE * 4)

__global__ __launch_bounds__(256) void attn_kernel(
    const float* __restrict__ mask, float* __restrict__ out)
{
    extern __shared__ float sm[];
    float* Qs = sm;                      // [64][68]
    float* Ks = sm + 64 * TSTRIDE;       // [64][68]
    float* Vs = sm + 2 * 64 * TSTRIDE;   // [64][68]
    float* Ps = sm + 3 * 64 * TSTRIDE;   // [64][68]

    const int b  = blockIdx.z;
    const int h  = blockIdx.y;
    const int qb = blockIdx.x;
    const int tid = threadIdx.x;
    const int ty = tid >> 4;   // 0..15  (row group)
    const int tx = tid & 15;   // 0..15  (col group)

    const float LOG2E  = 1.4426950408889634f;
    const float QSCALE = 0.125f * LOG2E;          // 1/sqrt(64) * log2(e)
    const float MSCALE = -60.0f * LOG2E;          // MASK_SCALE * log2(e)

    const float* qbase = g_q + ((size_t)(b * LL + qb * 64)) * DD + h * HDIM;
    const float* kbase = g_k + ((size_t)b * LL) * DD + h * HDIM;
    const float* vbase = g_v + ((size_t)b * LL) * DD + h * HDIM;
    const float* mbase = mask + (size_t)b * LL * LL + (size_t)(qb * 64) * LL;

    // Load Q tile (scaled)
#pragma unroll
    for (int i = 0; i < 4; i++) {
        int idx = tid + i * 256;
        int r = idx >> 4;
        int c = (idx & 15) * 4;
        float4 v = *(const float4*)(qbase + (size_t)r * DD + c);
        v.x *= QSCALE; v.y *= QSCALE; v.z *= QSCALE; v.w *= QSCALE;
        *(float4*)&Qs[r * TSTRIDE + c] = v;
    }

    float O[4][4];
#pragma unroll
    for (int i = 0; i < 4; i++)
#pragma unroll
        for (int j = 0; j < 4; j++) O[i][j] = 0.0f;
    float mrow[4] = {-INFINITY, -INFINITY, -INFINITY, -INFINITY};
    float lrow[4] = {0.0f, 0.0f, 0.0f, 0.0f};

    for (int kb = 0; kb < LL / 64; kb++) {
        // Guards: Q-load done (1st iter) / PV of previous iter done (later)
        __syncthreads();
        // Load K, V tiles
#pragma unroll
        for (int i = 0; i < 4; i++) {
            int idx = tid + i * 256;
            int r = idx >> 4;
            int c = (idx & 15) * 4;
            *(float4*)&Ks[r * TSTRIDE + c] =
                *(const float4*)(kbase + (size_t)(kb * 64 + r) * DD + c);
            *(float4*)&Vs[r * TSTRIDE + c] =
                *(const float4*)(vbase + (size_t)(kb * 64 + r) * DD + c);
        }
        __syncthreads();

        // S = Qs @ Ks^T   (4x4 per thread, rows ty+16i, cols tx+16j)
        float S[4][4];
#pragma unroll
        for (int i = 0; i < 4; i++)
#pragma unroll
            for (int j = 0; j < 4; j++) S[i][j] = 0.0f;

#pragma unroll
        for (int d = 0; d < HDIM; d += 4) {
            float4 q[4], k[4];
#pragma unroll
            for (int i = 0; i < 4; i++)
                q[i] = *(const float4*)&Qs[(ty + 16 * i) * TSTRIDE + d];
#pragma unroll
            for (int j = 0; j < 4; j++)
                k[j] = *(const float4*)&Ks[(tx + 16 * j) * TSTRIDE + d];
#pragma unroll
            for (int i = 0; i < 4; i++)
#pragma unroll
                for (int j = 0; j < 4; j++) {
                    S[i][j] = fmaf(q[i].x, k[j].x, S[i][j]);
                    S[i][j] = fmaf(q[i].y, k[j].y, S[i][j]);
                    S[i][j] = fmaf(q[i].z, k[j].z, S[i][j]);
                    S[i][j] = fmaf(q[i].w, k[j].w, S[i][j]);
                }
        }

        // Add mask * MSCALE (already in log2 domain)
#pragma unroll
        for (int i = 0; i < 4; i++) {
            const float* mr_ = mbase + (size_t)(ty + 16 * i) * LL + kb * 64;
#pragma unroll
            for (int j = 0; j < 4; j++)
                S[i][j] = fmaf(mr_[tx + 16 * j], MSCALE, S[i][j]);
        }

        // Online softmax (base 2). Row r=ty+16i lives on a contiguous 16-lane group.
#pragma unroll
        for (int i = 0; i < 4; i++) {
            float mx = fmaxf(fmaxf(S[i][0], S[i][1]), fmaxf(S[i][2], S[i][3]));
#pragma unroll
            for (int off = 1; off < 16; off <<= 1)
                mx = fmaxf(mx, __shfl_xor_sync(0xffffffffu, mx, off));
            float mnew = fmaxf(mrow[i], mx);
            float corr = exp2f(mrow[i] - mnew);   // 0 on first block
            mrow[i] = mnew;
            float p0 = exp2f(S[i][0] - mnew);
            float p1 = exp2f(S[i][1] - mnew);
            float p2 = exp2f(S[i][2] - mnew);
            float p3 = exp2f(S[i][3] - mnew);
            float rs = (p0 + p1) + (p2 + p3);
#pragma unroll
            for (int off = 1; off < 16; off <<= 1)
                rs += __shfl_xor_sync(0xffffffffu, rs, off);
            lrow[i] = lrow[i] * corr + rs;
            O[i][0] *= corr; O[i][1] *= corr; O[i][2] *= corr; O[i][3] *= corr;
            float* pr = &Ps[(ty + 16 * i) * TSTRIDE];
            pr[tx]      = p0;
            pr[tx + 16] = p1;
            pr[tx + 32] = p2;
            pr[tx + 48] = p3;
        }
        __syncthreads();

        // O += P @ V
#pragma unroll 8
        for (int j = 0; j < 64; j++) {
            float p0 = Ps[(ty)      * TSTRIDE + j];
            float p1 = Ps[(ty + 16) * TSTRIDE + j];
            float p2 = Ps[(ty + 32) * TSTRIDE + j];
            float p3 = Ps[(ty + 48) * TSTRIDE + j];
            const float* vr = &Vs[j * TSTRIDE];
            float v0 = vr[tx], v1 = vr[tx + 16], v2 = vr[tx + 32], v3 = vr[tx + 48];
            O[0][0] = fmaf(p0, v0, O[0][0]); O[0][1] = fmaf(p0, v1, O[0][1]);
            O[0][2] = fmaf(p0, v2, O[0][2]); O[0][3] = fmaf(p0, v3, O[0][3]);
            O[1][0] = fmaf(p1, v0, O[1][0]); O[1][1] = fmaf(p1, v1, O[1][1]);
            O[1][2] = fmaf(p1, v2, O[1][2]); O[1][3] = fmaf(p1, v3, O[1][3]);
            O[2][0] = fmaf(p2, v0, O[2][0]); O[2][1] = fmaf(p2, v1, O[2][1]);
            O[2][2] = fmaf(p2, v2, O[2][2]); O[2][3] = fmaf(p2, v3, O[2][3]);
            O[3][0] = fmaf(p3, v0, O[3][0]); O[3][1] = fmaf(p3, v1, O[3][1]);
            O[3][2] = fmaf(p3, v2, O[3][2]); O[3][3] = fmaf(p3, v3, O[3][3]);
        }
    }

    // Epilogue: out[b, qb*64 + r, h*64 + c] = O / l
    float* obase = out + ((size_t)(b * LL + qb * 64)) * DD + h * HDIM;
#pragma unroll
    for (int i = 0; i < 4; i++) {
        float inv = __frcp_rn(lrow[i]);
#pragma unroll
        for (int j = 0; j < 4; j++)
            obase[(size_t)(ty + 16 * i) * DD + tx + 16 * j] = O[i][j] * inv;
    }
}

// ---------------------------------------------------------------------------
// Launcher
// ---------------------------------------------------------------------------
extern "C" void kernel_launch(void* const* d_in, const int* in_sizes, int n_in,
                              void* d_out, int out_size)
{
    const float* x    = (const float*)d_in[0];
    const float* mask = (const float*)d_in[1];
    const float* Wq   = (const float*)d_in[2];
    const float* bq   = (const float*)d_in[3];
    const float* Wk   = (const float*)d_in[4];
    const float* bk   = (const float*)d_in[5];
    const float* Wv   = (const float*)d_in[6];
    const float* bv   = (const float*)d_in[7];
    float* out = (float*)d_out;

    dim3 g1(DD / 128, (BB * LL) / 128, 3);   // (8, 32, 3)
    qkv_gemm_kernel<<<g1, 256>>>(x, Wq, bq, Wk, bk, Wv, bv);

    cudaFuncSetAttribute(attn_kernel,
                         cudaFuncAttributeMaxDynamicSharedMemorySize, ATTN_SMEM);
    dim3 g2(LL / 64, HH, BB);                // (32, 16, 2)
    attn_kernel<<<g2, 256, ATTN_SMEM>>>(mask, out);
}

// round 3
// speedup vs baseline: 1.0355x; 1.0355x over previous
#include <cuda_runtime.h>
#include <math.h>
#include <stdint.h>

// Problem constants
#define BB   2
#define LL   2048
#define DD   1024
#define HH   16
#define HDIM 64

// Scratch for projected Q,K,V (each 16 MB fp32, static device mem)
__device__ float g_q[BB * LL * DD];
__device__ float g_k[BB * LL * DD];
__device__ float g_v[BB * LL * DD];

// ---------------------------------------------------------------------------
// Kernel 1: QKV projection. Y = X @ W + b, W selected by blockIdx.z.
// 128x128 tile, BK=16, double-buffered smem, 256 threads, 8x8 per thread.
// ---------------------------------------------------------------------------
__global__ __launch_bounds__(256, 2) void qkv_gemm_kernel(
    const float* __restrict__ X,
    const float* __restrict__ Wq, const float* __restrict__ bq,
    const float* __restrict__ Wk, const float* __restrict__ bk,
    const float* __restrict__ Wv, const float* __restrict__ bv)
{
    __shared__ float As[2][16 * 132];   // transposed: As[k][m]
    __shared__ float Bs[2][16 * 132];   // Bs[k][n]

    const float* W;
    const float* bias;
    float* out;
    if (blockIdx.z == 0)      { W = Wq; bias = bq; out = g_q; }
    else if (blockIdx.z == 1) { W = Wk; bias = bk; out = g_k; }
    else                      { W = Wv; bias = bv; out = g_v; }

    const int tid = threadIdx.x;
    const int m0 = blockIdx.y * 128;
    const int n0 = blockIdx.x * 128;
    const int tr = tid >> 4;
    const int tc = tid & 15;

    // A loader: 512 float4s over [128 rows x 16 cols], 2 per thread
    // B loader: 512 float4s over [16 rows x 128 cols], 2 per thread
    int ar[2], ak[2], br[2], bc[2];
#pragma unroll
    for (int s = 0; s < 2; s++) {
        int idx = tid + s * 256;
        ar[s] = idx >> 2;  ak[s] = (idx & 3) * 4;
        br[s] = idx >> 5;  bc[s] = (idx & 31) * 4;
    }

    float acc[8][8];
#pragma unroll
    for (int i = 0; i < 8; i++)
#pragma unroll
        for (int j = 0; j < 8; j++) acc[i][j] = 0.0f;

    // Preload stage 0
#pragma unroll
    for (int s = 0; s < 2; s++) {
        float4 av = *(const float4*)(X + (size_t)(m0 + ar[s]) * DD + ak[s]);
        float4 bv4 = *(const float4*)(W + (size_t)br[s] * DD + n0 + bc[s]);
        As[0][(ak[s] + 0) * 132 + ar[s]] = av.x;
        As[0][(ak[s] + 1) * 132 + ar[s]] = av.y;
        As[0][(ak[s] + 2) * 132 + ar[s]] = av.z;
        As[0][(ak[s] + 3) * 132 + ar[s]] = av.w;
        *(float4*)&Bs[0][br[s] * 132 + bc[s]] = bv4;
    }
    __syncthreads();

    int buf = 0;
    for (int k0 = 0; k0 < DD; k0 += 16) {
        const bool has_next = (k0 + 16) < DD;
        float4 a_n[2], b_n[2];
        if (has_next) {
#pragma unroll
            for (int s = 0; s < 2; s++) {
                a_n[s] = *(const float4*)(X + (size_t)(m0 + ar[s]) * DD + k0 + 16 + ak[s]);
                b_n[s] = *(const float4*)(W + (size_t)(k0 + 16 + br[s]) * DD + n0 + bc[s]);
            }
        }

#pragma unroll
        for (int kk = 0; kk < 16; kk++) {
            float4 a0 = *(const float4*)&As[buf][kk * 132 + tr * 4];
            float4 a1 = *(const float4*)&As[buf][kk * 132 + 64 + tr * 4];
            float4 b0 = *(const float4*)&Bs[buf][kk * 132 + tc * 4];
            float4 b1 = *(const float4*)&Bs[buf][kk * 132 + 64 + tc * 4];
            float a[8] = {a0.x, a0.y, a0.z, a0.w, a1.x, a1.y, a1.z, a1.w};
            float b[8] = {b0.x, b0.y, b0.z, b0.w, b1.x, b1.y, b1.z, b1.w};
#pragma unroll
            for (int i = 0; i < 8; i++)
#pragma unroll
                for (int j = 0; j < 8; j++)
                    acc[i][j] = fmaf(a[i], b[j], acc[i][j]);
        }

        if (has_next) {
            int nb = buf ^ 1;
#pragma unroll
            for (int s = 0; s < 2; s++) {
                As[nb][(ak[s] + 0) * 132 + ar[s]] = a_n[s].x;
                As[nb][(ak[s] + 1) * 132 + ar[s]] = a_n[s].y;
                As[nb][(ak[s] + 2) * 132 + ar[s]] = a_n[s].z;
                As[nb][(ak[s] + 3) * 132 + ar[s]] = a_n[s].w;
                *(float4*)&Bs[nb][br[s] * 132 + bc[s]] = b_n[s];
            }
            __syncthreads();
            buf = nb;
        }
    }

    float4 bias0 = *(const float4*)(bias + n0 + tc * 4);
    float4 bias1 = *(const float4*)(bias + n0 + 64 + tc * 4);
#pragma unroll
    for (int i = 0; i < 8; i++) {
        int mi = m0 + ((i < 4) ? (tr * 4 + i) : (64 + tr * 4 + (i - 4)));
        float4 r0, r1;
        r0.x = acc[i][0] + bias0.x; r0.y = acc[i][1] + bias0.y;
        r0.z = acc[i][2] + bias0.z; r0.w = acc[i][3] + bias0.w;
        r1.x = acc[i][4] + bias1.x; r1.y = acc[i][5] + bias1.y;
        r1.z = acc[i][6] + bias1.z; r1.w = acc[i][7] + bias1.w;
        *(float4*)(out + (size_t)mi * DD + n0 + tc * 4)      = r0;
        *(float4*)(out + (size_t)mi * DD + n0 + 64 + tc * 4) = r1;
    }
}

// ---------------------------------------------------------------------------
// Kernel 2: flash attention. BQ=128, BKV=128, HD=64, 256 threads.
// S tile: 8x8 per thread (rows ty+16i, cols tx+16j over 128 cols).
// O tile: 8x4 per thread (rows ty+16i, cols tx+16c over 64 cols).
// Online softmax in base-2; stats reduced over the 16-lane tx group.
// ---------------------------------------------------------------------------
#define KSTR 68    // Q/K/V smem row stride (floats)
#define PSTR 132   // P smem row stride (floats)
#define ATTN_SMEM ((3 * 128 * KSTR + 128 * PSTR) * 4)

__global__ __launch_bounds__(256, 1) void attn_kernel(
    const float* __restrict__ mask, float* __restrict__ out)
{
    extern __shared__ float sm[];
    float* Qs = sm;                       // [128][68]
    float* Ks = sm + 128 * KSTR;          // [128][68]
    float* Vs = sm + 2 * 128 * KSTR;      // [128][68]
    float* Ps = sm + 3 * 128 * KSTR;      // [128][132]

    const int b  = blockIdx.z;
    const int h  = blockIdx.y;
    const int qb = blockIdx.x;
    const int tid = threadIdx.x;
    const int ty = tid >> 4;   // 0..15
    const int tx = tid & 15;   // 0..15

    const float LOG2E  = 1.4426950408889634f;
    const float QSCALE = 0.125f * LOG2E;
    const float MSCALE = -60.0f * LOG2E;

    const float* qbase = g_q + ((size_t)(b * LL + qb * 128)) * DD + h * HDIM;
    const float* kbase = g_k + ((size_t)b * LL) * DD + h * HDIM;
    const float* vbase = g_v + ((size_t)b * LL) * DD + h * HDIM;
    const float* mbase = mask + (size_t)b * LL * LL + (size_t)(qb * 128) * LL;

    // Load Q tile (128x64), scaled
#pragma unroll
    for (int i = 0; i < 8; i++) {
        int idx = tid + i * 256;
        int r = idx >> 4;
        int c = (idx & 15) * 4;
        float4 v = *(const float4*)(qbase + (size_t)r * DD + c);
        v.x *= QSCALE; v.y *= QSCALE; v.z *= QSCALE; v.w *= QSCALE;
        *(float4*)&Qs[r * KSTR + c] = v;
    }

    float O[8][4];
#pragma unroll
    for (int i = 0; i < 8; i++)
#pragma unroll
        for (int c = 0; c < 4; c++) O[i][c] = 0.0f;
    float mrow[8], lrow[8];
#pragma unroll
    for (int i = 0; i < 8; i++) { mrow[i] = -INFINITY; lrow[i] = 0.0f; }

    for (int kb = 0; kb < LL / 128; kb++) {
        __syncthreads();   // prev PV done / Q loaded
#pragma unroll
        for (int i = 0; i < 8; i++) {
            int idx = tid + i * 256;
            int r = idx >> 4;
            int c = (idx & 15) * 4;
            *(float4*)&Ks[r * KSTR + c] =
                *(const float4*)(kbase + (size_t)(kb * 128 + r) * DD + c);
            *(float4*)&Vs[r * KSTR + c] =
                *(const float4*)(vbase + (size_t)(kb * 128 + r) * DD + c);
        }
        __syncthreads();

        // S = Qs @ Ks^T (8x8 per thread), float2 operand loads
        float S[8][8];
#pragma unroll
        for (int i = 0; i < 8; i++)
#pragma unroll
            for (int j = 0; j < 8; j++) S[i][j] = 0.0f;

#pragma unroll 8
        for (int d = 0; d < HDIM; d += 2) {
            float2 q[8], k[8];
#pragma unroll
            for (int i = 0; i < 8; i++)
                q[i] = *(const float2*)&Qs[(ty + 16 * i) * KSTR + d];
#pragma unroll
            for (int j = 0; j < 8; j++)
                k[j] = *(const float2*)&Ks[(tx + 16 * j) * KSTR + d];
#pragma unroll
            for (int i = 0; i < 8; i++)
#pragma unroll
                for (int j = 0; j < 8; j++) {
                    S[i][j] = fmaf(q[i].x, k[j].x, S[i][j]);
                    S[i][j] = fmaf(q[i].y, k[j].y, S[i][j]);
                }
        }

        // Add mask * MSCALE (base-2 domain)
#pragma unroll
        for (int i = 0; i < 8; i++) {
            const float* mr_ = mbase + (size_t)(ty + 16 * i) * LL + kb * 128;
#pragma unroll
            for (int j = 0; j < 8; j++)
                S[i][j] = fmaf(mr_[tx + 16 * j], MSCALE, S[i][j]);
        }

        // Online softmax per row; write P to smem
#pragma unroll
        for (int i = 0; i < 8; i++) {
            float mx = S[i][0];
#pragma unroll
            for (int j = 1; j < 8; j++) mx = fmaxf(mx, S[i][j]);
#pragma unroll
            for (int off = 1; off < 16; off <<= 1)
                mx = fmaxf(mx, __shfl_xor_sync(0xffffffffu, mx, off));
            float mnew = fmaxf(mrow[i], mx);
            float corr = exp2f(mrow[i] - mnew);
            mrow[i] = mnew;
            float rs = 0.0f;
#pragma unroll
            for (int j = 0; j < 8; j++) {
                S[i][j] = exp2f(S[i][j] - mnew);
                rs += S[i][j];
            }
#pragma unroll
            for (int off = 1; off < 16; off <<= 1)
                rs += __shfl_xor_sync(0xffffffffu, rs, off);
            lrow[i] = lrow[i] * corr + rs;
#pragma unroll
            for (int c = 0; c < 4; c++) O[i][c] *= corr;
            float* pr = &Ps[(ty + 16 * i) * PSTR];
#pragma unroll
            for (int j = 0; j < 8; j++) pr[tx + 16 * j] = S[i][j];
        }
        __syncthreads();

        // O += P @ V  (rows ty+16i, cols tx+16c, c<4)
#pragma unroll 2
        for (int j0 = 0; j0 < 128; j0 += 4) {
            float4 p[8];
#pragma unroll
            for (int i = 0; i < 8; i++)
                p[i] = *(const float4*)&Ps[(ty + 16 * i) * PSTR + j0];
#pragma unroll
            for (int jj = 0; jj < 4; jj++) {
                float v[4];
#pragma unroll
                for (int c = 0; c < 4; c++)
                    v[c] = Vs[(j0 + jj) * KSTR + tx + 16 * c];
#pragma unroll
                for (int i = 0; i < 8; i++) {
                    float pi = (jj == 0) ? p[i].x : (jj == 1) ? p[i].y
                             : (jj == 2) ? p[i].z : p[i].w;
#pragma unroll
                    for (int c = 0; c < 4; c++)
                        O[i][c] = fmaf(pi, v[c], O[i][c]);
                }
            }
        }
    }

    // Epilogue: cols tx+16c (c<4) cover head dim 64
    float* obase = out + ((size_t)(b * LL + qb * 128)) * DD + h * HDIM;
#pragma unroll
    for (int i = 0; i < 8; i++) {
        float inv = __frcp_rn(lrow[i]);
#pragma unroll
        for (int c = 0; c < 4; c++)
            obase[(size_t)(ty + 16 * i) * DD + tx + 16 * c] = O[i][c] * inv;
    }
}

// ---------------------------------------------------------------------------
// Launcher
// ---------------------------------------------------------------------------
extern "C" void kernel_launch(void* const* d_in, const int* in_sizes, int n_in,
                              void* d_out, int out_size)
{
    const float* x    = (const float*)d_in[0];
    const float* mask = (const float*)d_in[1];
    const float* Wq   = (const float*)d_in[2];
    const float* bq   = (const float*)d_in[3];
    const float* Wk   = (const float*)d_in[4];
    const float* bk   = (const float*)d_in[5];
    const float* Wv   = (const float*)d_in[6];
    const float* bv   = (const float*)d_in[7];
    float* out = (float*)d_out;

    dim3 g1(DD / 128, (BB * LL) / 128, 3);   // (8, 32, 3)
    qkv_gemm_kernel<<<g1, 256>>>(x, Wq, bq, Wk, bk, Wv, bv);

    cudaFuncSetAttribute(attn_kernel,
                         cudaFuncAttributeMaxDynamicSharedMemorySize, ATTN_SMEM);
    dim3 g2(LL / 128, HH, BB);               // (16, 16, 2)
    attn_kernel<<<g2, 256, ATTN_SMEM>>>(mask, out);
}

// round 6
// speedup vs baseline: 1.1671x; 1.1271x over previous
#include <cuda_runtime.h>
#include <cuda_bf16.h>
#include <math.h>
#include <stdint.h>

// Problem constants
#define BB   2
#define LL   2048
#define DD   1024
#define HH   16
#define HDIM 64

// Scratch (static device memory; allocation-guard safe)
__device__ __align__(256) float g_q[BB * LL * DD];
__device__ __align__(256) float g_k[BB * LL * DD];
__device__ __align__(256) float g_v[BB * LL * DD];
__device__ __align__(256) __nv_bfloat16 g_xhi[BB * LL * DD];
__device__ __align__(256) __nv_bfloat16 g_xlo[BB * LL * DD];
__device__ __align__(256) __nv_bfloat16 g_wthi[3 * DD * DD];
__device__ __align__(256) __nv_bfloat16 g_wtlo[3 * DD * DD];

// ---------------------------------------------------------------------------
// PTX helpers (portable to plain compute_103 target: mma.sync + cp.async)
// ---------------------------------------------------------------------------
__device__ __forceinline__ uint32_t smem_u32(const void* p) {
    uint32_t a;
    asm("{ .reg .u64 t; cvta.to.shared.u64 t, %1; cvt.u32.u64 %0, t; }"
        : "=r"(a) : "l"(p));
    return a;
}

#define CP_ASYNC16(dst, src) \
    asm volatile("cp.async.cg.shared.global [%0], [%1], 16;" \
                 :: "r"(dst), "l"(src) : "memory")
#define CP_COMMIT() asm volatile("cp.async.commit_group;" ::: "memory")
#define CP_WAIT1()  asm volatile("cp.async.wait_group 1;" ::: "memory")

#define LDSM_X4(r0, r1, r2, r3, addr) \
    asm volatile("ldmatrix.sync.aligned.m8n8.x4.shared.b16 {%0,%1,%2,%3}, [%4];" \
                 : "=r"(r0), "=r"(r1), "=r"(r2), "=r"(r3) : "r"(addr))

#define MMA_BF16(d, a, b0, b1) \
    asm volatile("mma.sync.aligned.m16n8k16.row.col.f32.bf16.bf16.f32 " \
                 "{%0,%1,%2,%3}, {%4,%5,%6,%7}, {%8,%9}, {%0,%1,%2,%3};" \
                 : "+f"((d)[0]), "+f"((d)[1]), "+f"((d)[2]), "+f"((d)[3]) \
                 : "r"((a)[0]), "r"((a)[1]), "r"((a)[2]), "r"((a)[3]), \
                   "r"(b0), "r"(b1))

// ---------------------------------------------------------------------------
// Pre-pass 1: split X (fp32) into bf16 hi/lo
// ---------------------------------------------------------------------------
__global__ __launch_bounds__(256) void split_x_kernel(const float* __restrict__ X)
{
    const int total = BB * LL * DD;
    for (int idx = blockIdx.x * blockDim.x * 8 + threadIdx.x; idx < total;
         idx += gridDim.x * blockDim.x * 8) {
#pragma unroll
        for (int s = 0; s < 8; s++) {
            int i = idx + s * 256;
            if (i < total) {
                float x = X[i];
                __nv_bfloat16 hi = __float2bfloat16(x);
                g_xhi[i] = hi;
                g_xlo[i] = __float2bfloat16(x - __bfloat162float(hi));
            }
        }
    }
}

// ---------------------------------------------------------------------------
// Pre-pass 2: transpose W [k][n] -> Wt [n][k], split into bf16 hi/lo
// ---------------------------------------------------------------------------
__global__ __launch_bounds__(256) void wsplit_kernel(
    const float* __restrict__ Wq, const float* __restrict__ Wk,
    const float* __restrict__ Wv)
{
    __shared__ float t[32][33];
    const float* W = (blockIdx.z == 0) ? Wq : (blockIdx.z == 1) ? Wk : Wv;
    const size_t off = (size_t)blockIdx.z * DD * DD;
    int bx = blockIdx.x * 32;   // n tile
    int by = blockIdx.y * 32;   // k tile
#pragma unroll
    for (int j = 0; j < 4; j++)
        t[threadIdx.y + 8 * j][threadIdx.x] =
            W[(size_t)(by + threadIdx.y + 8 * j) * DD + bx + threadIdx.x];
    __syncthreads();
#pragma unroll
    for (int j = 0; j < 4; j++) {
        int n = bx + threadIdx.y + 8 * j;
        int k = by + threadIdx.x;
        float v = t[threadIdx.x][threadIdx.y + 8 * j];
        __nv_bfloat16 hi = __float2bfloat16(v);
        g_wthi[off + (size_t)n * DD + k] = hi;
        g_wtlo[off + (size_t)n * DD + k] = __float2bfloat16(v - __bfloat162float(hi));
    }
}

// ---------------------------------------------------------------------------
// Kernel: QKV GEMM via mma.sync bf16 hi/lo (3 terms). 128x128 tile, BK=32,
// 256 threads = 8 warps as 2(m)x4(n), 64x32 per warp. cp.async 2-stage pipe.
// Smem rows padded to 80B (32 bf16 data + 16B pad): ldmatrix conflict-free.
// ---------------------------------------------------------------------------
#define RSTR   80                 // smem row stride, bytes
#define TILE_B (128 * RSTR)       // 10240 B per tile
#define STG    (4 * TILE_B)       // Ahi, Alo, Bhi, Blo
#define OA_HI  0
#define OA_LO  TILE_B
#define OB_HI  (2 * TILE_B)
#define OB_LO  (3 * TILE_B)
#define GEMM_SMEM (2 * STG)       // 81920 B

__global__ __launch_bounds__(256) void qkv_mma_kernel(
    const float* __restrict__ bq, const float* __restrict__ bk,
    const float* __restrict__ bv)
{
    extern __shared__ char smem[];
    const uint32_t sbase = smem_u32(smem);
    const int tid  = threadIdx.x;
    const int lane = tid & 31;
    const int wid  = tid >> 5;
    const int wm   = wid & 1;     // 0..1  -> m offset wm*64
    const int wn   = wid >> 1;    // 0..3  -> n offset wn*32

    const int n0  = blockIdx.x * 128;
    const int m0  = blockIdx.y * 128;
    const int mat = blockIdx.z;

    const __nv_bfloat16* Bh = g_wthi + (size_t)mat * DD * DD;
    const __nv_bfloat16* Bl = g_wtlo + (size_t)mat * DD * DD;
    const float* bias = (mat == 0) ? bq : (mat == 1) ? bk : bv;
    float* out = (mat == 0) ? g_q : (mat == 1) ? g_k : g_v;

    // Loader indices: 512 x 16B per tile per chunk; 2 iters/thread/tile.
    const int lr0 = (tid + 0)   >> 2, lc0 = (tid & 3) * 16;
    const int lr1 = (tid + 256) >> 2, lc1 = lc0;   // same cg, rows 64..127

    float acc[4][4][4];
#pragma unroll
    for (int i = 0; i < 4; i++)
#pragma unroll
        for (int j = 0; j < 4; j++)
#pragma unroll
            for (int r = 0; r < 4; r++) acc[i][j][r] = 0.0f;

    // Issue loads for chunk c into stage s
    auto issue = [&](int c, int s) {
        const uint32_t sb = sbase + s * STG;
        const int k0 = c * 32;
        const int cgk0 = lc0 / 2;   // bf16 element offset of 16B group
        // rows lr0 and lr1 for each of the 4 tiles
        CP_ASYNC16(sb + OA_HI + lr0 * RSTR + lc0, g_xhi + (size_t)(m0 + lr0) * DD + k0 + cgk0);
        CP_ASYNC16(sb + OA_HI + lr1 * RSTR + lc1, g_xhi + (size_t)(m0 + lr1) * DD + k0 + cgk0);
        CP_ASYNC16(sb + OA_LO + lr0 * RSTR + lc0, g_xlo + (size_t)(m0 + lr0) * DD + k0 + cgk0);
        CP_ASYNC16(sb + OA_LO + lr1 * RSTR + lc1, g_xlo + (size_t)(m0 + lr1) * DD + k0 + cgk0);
        CP_ASYNC16(sb + OB_HI + lr0 * RSTR + lc0, Bh + (size_t)(n0 + lr0) * DD + k0 + cgk0);
        CP_ASYNC16(sb + OB_HI + lr1 * RSTR + lc1, Bh + (size_t)(n0 + lr1) * DD + k0 + cgk0);
        CP_ASYNC16(sb + OB_LO + lr0 * RSTR + lc0, Bl + (size_t)(n0 + lr0) * DD + k0 + cgk0);
        CP_ASYNC16(sb + OB_LO + lr1 * RSTR + lc1, Bl + (size_t)(n0 + lr1) * DD + k0 + cgk0);
    };

    issue(0, 0); CP_COMMIT();
    issue(1, 1); CP_COMMIT();

    const int NCHUNK = DD / 32;   // 32
    for (int c = 0; c < NCHUNK; c++) {
        const int buf = c & 1;
        CP_WAIT1();
        __syncthreads();

        const uint32_t sb = sbase + buf * STG;
        // ldmatrix base addresses for this warp
        const uint32_t a_row = (wm * 64 + (lane & 15)) * RSTR + (lane >> 4) * 16;
        const uint32_t b_row = (wn * 32 + (lane & 7) + ((lane >> 4) & 1) * 8) * RSTR
                             + ((lane >> 3) & 1) * 16;
#pragma unroll
        for (int ks = 0; ks < 2; ks++) {
            const uint32_t ko = ks * 32;
            uint32_t ahi[4][4], alo[4][4], bhi[8], blo[8];
#pragma unroll
            for (int i = 0; i < 4; i++) {
                LDSM_X4(ahi[i][0], ahi[i][1], ahi[i][2], ahi[i][3],
                        sb + OA_HI + a_row + i * 16 * RSTR + ko);
                LDSM_X4(alo[i][0], alo[i][1], alo[i][2], alo[i][3],
                        sb + OA_LO + a_row + i * 16 * RSTR + ko);
            }
#pragma unroll
            for (int p = 0; p < 2; p++) {
                LDSM_X4(bhi[4 * p], bhi[4 * p + 1], bhi[4 * p + 2], bhi[4 * p + 3],
                        sb + OB_HI + b_row + p * 16 * RSTR + ko);
                LDSM_X4(blo[4 * p], blo[4 * p + 1], blo[4 * p + 2], blo[4 * p + 3],
                        sb + OB_LO + b_row + p * 16 * RSTR + ko);
            }
#pragma unroll
            for (int i = 0; i < 4; i++)
#pragma unroll
                for (int j = 0; j < 4; j++) {
                    const int bb0 = 4 * (j >> 1) + (j & 1) * 2;
                    MMA_BF16(acc[i][j], ahi[i], bhi[bb0], bhi[bb0 + 1]);
                    MMA_BF16(acc[i][j], ahi[i], blo[bb0], blo[bb0 + 1]);
                    MMA_BF16(acc[i][j], alo[i], bhi[bb0], bhi[bb0 + 1]);
                }
        }
        __syncthreads();
        if (c + 2 < NCHUNK) issue(c + 2, buf);
        CP_COMMIT();   // uniform commit keeps wait_group accounting exact
    }

    // Epilogue: acc fragment (i,j): rows m0+wm*64+i*16+lane/4 (+8),
    // cols n0+wn*32+j*8+2*(lane&3). float2 stores, bias added.
#pragma unroll
    for (int j = 0; j < 4; j++) {
        const int col = n0 + wn * 32 + j * 8 + (lane & 3) * 2;
        const float b0 = bias[col], b1 = bias[col + 1];
#pragma unroll
        for (int i = 0; i < 4; i++) {
            const int row = m0 + wm * 64 + i * 16 + (lane >> 2);
            *(float2*)(out + (size_t)row * DD + col) =
                make_float2(acc[i][j][0] + b0, acc[i][j][1] + b1);
            *(float2*)(out + (size_t)(row + 8) * DD + col) =
                make_float2(acc[i][j][2] + b0, acc[i][j][3] + b1);
        }
    }
}

// ---------------------------------------------------------------------------
// Kernel: flash attention. BQ=BKV=128, HD=64, 512 threads (16 warps).
// S tile: 8x4 per thread (rows ty+16i, cols tx+32j); O tile: 8x2.
// ty = warp id: each warp owns its rows -> full-warp shfl reductions.
// ---------------------------------------------------------------------------
#define KSTR 66    // Q/K/V smem row stride (floats): conflict-free
#define PSTR 132   // P smem row stride
#define ATTN_SMEM ((3 * 128 * KSTR + 128 * PSTR) * 4)

__global__ __launch_bounds__(512, 1) void attn_kernel(
    const float* __restrict__ mask, float* __restrict__ out)
{
    extern __shared__ float sm[];
    float* Qs = sm;                       // [128][66]
    float* Ks = sm + 128 * KSTR;          // [128][66]
    float* Vs = sm + 2 * 128 * KSTR;      // [128][66]
    float* Ps = sm + 3 * 128 * KSTR;      // [128][132]

    const int b  = blockIdx.z;
    const int h  = blockIdx.y;
    const int qb = blockIdx.x;
    const int tid = threadIdx.x;
    const int ty = tid >> 5;   // 0..15 (warp)
    const int tx = tid & 31;   // lane

    const float LOG2E  = 1.4426950408889634f;
    const float QSCALE = 0.125f * LOG2E;
    const float MSCALE = -60.0f * LOG2E;

    const float* qbase = g_q + ((size_t)(b * LL + qb * 128)) * DD + h * HDIM;
    const float* kbase = g_k + ((size_t)b * LL) * DD + h * HDIM;
    const float* vbase = g_v + ((size_t)b * LL) * DD + h * HDIM;
    const float* mbase = mask + (size_t)b * LL * LL + (size_t)(qb * 128) * LL;

    // Load Q tile (128x64), scaled
#pragma unroll
    for (int i = 0; i < 4; i++) {
        int idx = tid + i * 512;
        int r = idx >> 4;
        int c = (idx & 15) * 4;
        float4 v = *(const float4*)(qbase + (size_t)r * DD + c);
        float* dst = &Qs[r * KSTR + c];
        *(float2*)(dst)     = make_float2(v.x * QSCALE, v.y * QSCALE);
        *(float2*)(dst + 2) = make_float2(v.z * QSCALE, v.w * QSCALE);
    }

    float O[8][2];
#pragma unroll
    for (int i = 0; i < 8; i++) { O[i][0] = 0.0f; O[i][1] = 0.0f; }
    float mrow[8], lrow[8];
#pragma unroll
    for (int i = 0; i < 8; i++) { mrow[i] = -INFINITY; lrow[i] = 0.0f; }

    for (int kb = 0; kb < LL / 128; kb++) {
        __syncthreads();
#pragma unroll
        for (int i = 0; i < 4; i++) {
            int idx = tid + i * 512;
            int r = idx >> 4;
            int c = (idx & 15) * 4;
            float4 kv = *(const float4*)(kbase + (size_t)(kb * 128 + r) * DD + c);
            float4 vv = *(const float4*)(vbase + (size_t)(kb * 128 + r) * DD + c);
            float* kd = &Ks[r * KSTR + c];
            float* vd = &Vs[r * KSTR + c];
            *(float2*)(kd)     = make_float2(kv.x, kv.y);
            *(float2*)(kd + 2) = make_float2(kv.z, kv.w);
            *(float2*)(vd)     = make_float2(vv.x, vv.y);
            *(float2*)(vd + 2) = make_float2(vv.z, vv.w);
        }
        __syncthreads();

        // S = Qs @ Ks^T (8x4 per thread)
        float S[8][4];
#pragma unroll
        for (int i = 0; i < 8; i++)
#pragma unroll
            for (int j = 0; j < 4; j++) S[i][j] = 0.0f;

#pragma unroll 8
        for (int d = 0; d < HDIM; d += 2) {
            float2 q[8], k[4];
#pragma unroll
            for (int i = 0; i < 8; i++)
                q[i] = *(const float2*)&Qs[(ty + 16 * i) * KSTR + d];
#pragma unroll
            for (int j = 0; j < 4; j++)
                k[j] = *(const float2*)&Ks[(tx + 32 * j) * KSTR + d];
#pragma unroll
            for (int i = 0; i < 8; i++)
#pragma unroll
                for (int j = 0; j < 4; j++) {
                    S[i][j] = fmaf(q[i].x, k[j].x, S[i][j]);
                    S[i][j] = fmaf(q[i].y, k[j].y, S[i][j]);
                }
        }

        // Add mask * MSCALE (base-2 domain)
#pragma unroll
        for (int i = 0; i < 8; i++) {
            const float* mr_ = mbase + (size_t)(ty + 16 * i) * LL + kb * 128;
#pragma unroll
            for (int j = 0; j < 4; j++)
                S[i][j] = fmaf(mr_[tx + 32 * j], MSCALE, S[i][j]);
        }

        // Online softmax per row (full-warp reductions)
#pragma unroll
        for (int i = 0; i < 8; i++) {
            float mx = fmaxf(fmaxf(S[i][0], S[i][1]), fmaxf(S[i][2], S[i][3]));
#pragma unroll
            for (int off = 1; off < 32; off <<= 1)
                mx = fmaxf(mx, __shfl_xor_sync(0xffffffffu, mx, off));
            float mnew = fmaxf(mrow[i], mx);
            float corr = exp2f(mrow[i] - mnew);
            mrow[i] = mnew;
            float rs = 0.0f;
#pragma unroll
            for (int j = 0; j < 4; j++) {
                S[i][j] = exp2f(S[i][j] - mnew);
                rs += S[i][j];
            }
#pragma unroll
            for (int off = 1; off < 32; off <<= 1)
                rs += __shfl_xor_sync(0xffffffffu, rs, off);
            lrow[i] = lrow[i] * corr + rs;
            O[i][0] *= corr;
            O[i][1] *= corr;
            float* pr = &Ps[(ty + 16 * i) * PSTR];
#pragma unroll
            for (int j = 0; j < 4; j++) pr[tx + 32 * j] = S[i][j];
        }
        __syncthreads();

        // O += P @ V (rows ty+16i, cols tx+32c, c<2)
#pragma unroll 2
        for (int j0 = 0; j0 < 128; j0 += 4) {
            float4 p[8];
#pragma unroll
            for (int i = 0; i < 8; i++)
                p[i] = *(const float4*)&Ps[(ty + 16 * i) * PSTR + j0];
#pragma unroll
            for (int jj = 0; jj < 4; jj++) {
                float v0 = Vs[(j0 + jj) * KSTR + tx];
                float v1 = Vs[(j0 + jj) * KSTR + tx + 32];
#pragma unroll
                for (int i = 0; i < 8; i++) {
                    float pi = (jj == 0) ? p[i].x : (jj == 1) ? p[i].y
                             : (jj == 2) ? p[i].z : p[i].w;
                    O[i][0] = fmaf(pi, v0, O[i][0]);
                    O[i][1] = fmaf(pi, v1, O[i][1]);
                }
            }
        }
    }

    // Epilogue
    float* obase = out + ((size_t)(b * LL + qb * 128)) * DD + h * HDIM;
#pragma unroll
    for (int i = 0; i < 8; i++) {
        float inv = __frcp_rn(lrow[i]);
        obase[(size_t)(ty + 16 * i) * DD + tx]      = O[i][0] * inv;
        obase[(size_t)(ty + 16 * i) * DD + tx + 32] = O[i][1] * inv;
    }
}

// ---------------------------------------------------------------------------
// Launcher
// ---------------------------------------------------------------------------
extern "C" void kernel_launch(void* const* d_in, const int* in_sizes, int n_in,
                              void* d_out, int out_size)
{
    const float* x    = (const float*)d_in[0];
    const float* mask = (const float*)d_in[1];
    const float* Wq   = (const float*)d_in[2];
    const float* bq   = (const float*)d_in[3];
    const float* Wk   = (const float*)d_in[4];
    const float* bk   = (const float*)d_in[5];
    const float* Wv   = (const float*)d_in[6];
    const float* bv   = (const float*)d_in[7];
    float* out = (float*)d_out;

    split_x_kernel<<<2048, 256>>>(x);
    wsplit_kernel<<<dim3(32, 32, 3), dim3(32, 8)>>>(Wq, Wk, Wv);

    cudaFuncSetAttribute(qkv_mma_kernel,
                         cudaFuncAttributeMaxDynamicSharedMemorySize, GEMM_SMEM);
    qkv_mma_kernel<<<dim3(8, 32, 3), 256, GEMM_SMEM>>>(bq, bk, bv);

    cudaFuncSetAttribute(attn_kernel,
                         cudaFuncAttributeMaxDynamicSharedMemorySize, ATTN_SMEM);
    attn_kernel<<<dim3(16, 16, 2), 512, ATTN_SMEM>>>(mask, out);
}